// round 6
// baseline (speedup 1.0000x reference)
#include <cuda_runtime.h>
#include <cuda_bf16.h>
#include <cstdint>
#include <math.h>

// Problem constants
#define LSEQ 48
#define BATCH 8192
#define EDIM 50
#define HDIM 512
#define VOCAB 128
#define NG   (4 * HDIM)      // 2048 packed gate columns (n = h*4 + g)
#define KH   512             // K per segment
#define NCH  24              // 3 segments * 8 chunks of 64
#define NSTG 3               // pipeline stages
#define STG_BYTES 16384      // bytes per stage per operand

// ---------------- scratch (static __device__ arrays; no allocation) ----------
__device__ __nv_bfloat16 g_Whi[(size_t)NG * KH];     // W_hh packed [n][k] hi
__device__ __nv_bfloat16 g_Wlo[(size_t)NG * KH];     // lo
__device__ __nv_bfloat16 g_Wohi[(size_t)VOCAB * KH]; // W_out [v][k] hi
__device__ __nv_bfloat16 g_Wolo[(size_t)VOCAB * KH]; // lo
__device__ float g_bsum[NG];                         // b_ih + b_hh, packed order
__device__ float g_Xg[(size_t)VOCAB * NG];           // emb @ W_ih^T, packed order
__device__ __nv_bfloat16 g_Ahi[(size_t)(LSEQ + 1) * BATCH * KH];  // h_t [t][b][k] hi
__device__ __nv_bfloat16 g_Alo[(size_t)(LSEQ + 1) * BATCH * KH];  // lo
__device__ float g_C[(size_t)BATCH * HDIM];          // cell state [b][h] fp32

// ---------------- helpers ----------------------------------------------------
__device__ __forceinline__ uint32_t smem_u32(const void* p) {
    return (uint32_t)__cvta_generic_to_shared(p);
}
#define CP16(dst, src) asm volatile("cp.async.cg.shared.global [%0], [%1], 16;" :: "r"(dst), "l"(src))
#define CP_COMMIT()    asm volatile("cp.async.commit_group;")
#define CP_WAIT0()     asm volatile("cp.async.wait_group 0;" ::: "memory")
#define CP_WAIT1()     asm volatile("cp.async.wait_group 1;" ::: "memory")

__device__ __forceinline__ void ldsm4(uint32_t& r0, uint32_t& r1, uint32_t& r2, uint32_t& r3,
                                      uint32_t addr) {
    asm volatile("ldmatrix.sync.aligned.m8n8.x4.shared.b16 {%0,%1,%2,%3}, [%4];"
                 : "=r"(r0), "=r"(r1), "=r"(r2), "=r"(r3) : "r"(addr));
}
__device__ __forceinline__ void mma16816(float* d, const uint32_t* a, uint32_t b0, uint32_t b1) {
    asm volatile("mma.sync.aligned.m16n8k16.row.col.f32.bf16.bf16.f32 "
                 "{%0,%1,%2,%3}, {%4,%5,%6,%7}, {%8,%9}, {%0,%1,%2,%3};"
                 : "+f"(d[0]), "+f"(d[1]), "+f"(d[2]), "+f"(d[3])
                 : "r"(a[0]), "r"(a[1]), "r"(a[2]), "r"(a[3]), "r"(b0), "r"(b1));
}
__device__ __forceinline__ float sigm(float x) { return 1.0f / (1.0f + __expf(-x)); }
__device__ __forceinline__ float tanh_fast(float x) { return 2.0f * sigm(2.0f * x) - 1.0f; }
__device__ __forceinline__ void split_bf16(float x, __nv_bfloat16& hi, __nv_bfloat16& lo) {
    hi = __float2bfloat16_rn(x);
    lo = __float2bfloat16_rn(x - __bfloat162float(hi));
}

// ---------------- cp.async tile loader (A and B chunk -> swizzled SMEM) -------
// chunk 0-7: Ahi*Bhi, 8-15: Ahi*Blo, 16-23: Alo*Bhi.  BK=64 bf16 = 128B rows.
__device__ __forceinline__ void issue_tile_loads(
    int chunk, uint32_t Asm, uint32_t Bsm,
    const __nv_bfloat16* __restrict__ Ahi, const __nv_bfloat16* __restrict__ Alo,
    const __nv_bfloat16* __restrict__ Bhi, const __nv_bfloat16* __restrict__ Blo,
    int bm0, int n0, int tid)
{
    const int seg = chunk >> 3;
    const int k0  = (chunk & 7) * 64;
    const int s   = chunk % NSTG;
    const __nv_bfloat16* Ab = (seg < 2) ? Ahi : Alo;
    const __nv_bfloat16* Bb = (seg == 1) ? Blo : Bhi;
    const int r  = tid >> 1;             // 0..127
    const int j0 = (tid & 1) * 4;        // 0 or 4 (16B chunks)
    const __nv_bfloat16* ga = Ab + ((size_t)(bm0 + r) << 9) + k0 + j0 * 8;
    const __nv_bfloat16* gb = Bb + ((size_t)(n0 + r) << 9) + k0 + j0 * 8;
    const uint32_t abase = Asm + s * STG_BYTES, bbase = Bsm + s * STG_BYTES;
    #pragma unroll
    for (int j = 0; j < 4; ++j) {
        uint32_t off = r * 128 + (j0 + j) * 16;
        uint32_t sw  = off ^ ((off >> 3) & 0x70);
        CP16(abase + sw, ga + j * 8);
        CP16(bbase + sw, gb + j * 8);
    }
    CP_COMMIT();
}

// ---------------- one BK=64 chunk of HMMA compute ------------------------------
__device__ __forceinline__ void compute_chunk(uint32_t sAb, uint32_t sBb,
                                              int wm, int wn, int lane,
                                              float acc[4][4][4]) {
    #pragma unroll
    for (int kk = 0; kk < 4; ++kk) {
        uint32_t a[4][4];
        #pragma unroll
        for (int mi = 0; mi < 4; ++mi) {
            int r  = wm + 16 * mi + (lane & 15);
            int kb = kk * 32 + ((lane >> 4) << 4);
            uint32_t off = (uint32_t)(r * 128 + kb);
            off ^= (off >> 3) & 0x70;
            ldsm4(a[mi][0], a[mi][1], a[mi][2], a[mi][3], sAb + off);
        }
        uint32_t b[2][4];
        #pragma unroll
        for (int nj2 = 0; nj2 < 2; ++nj2) {
            int r  = wn + nj2 * 16 + ((lane >> 4) << 3) + (lane & 7);
            int kb = kk * 32 + ((lane & 8) ? 16 : 0);
            uint32_t off = (uint32_t)(r * 128 + kb);
            off ^= (off >> 3) & 0x70;
            ldsm4(b[nj2][0], b[nj2][1], b[nj2][2], b[nj2][3], sBb + off);
        }
        #pragma unroll
        for (int mi = 0; mi < 4; ++mi)
            #pragma unroll
            for (int nj = 0; nj < 4; ++nj)
                mma16816(acc[mi][nj], a[mi],
                         b[nj >> 1][(nj & 1) * 2], b[nj >> 1][(nj & 1) * 2 + 1]);
    }
}

// ---------------- 3-stage mainloop: one barrier per chunk ----------------------
__device__ __forceinline__ void run_mainloop(
    const __nv_bfloat16* __restrict__ Ahi, const __nv_bfloat16* __restrict__ Alo,
    const __nv_bfloat16* __restrict__ Bhi, const __nv_bfloat16* __restrict__ Blo,
    int bm0, int n0, int tid, int lane, int wm, int wn,
    uint32_t Asm, uint32_t Bsm, float acc[4][4][4])
{
    issue_tile_loads(0, Asm, Bsm, Ahi, Alo, Bhi, Blo, bm0, n0, tid);
    issue_tile_loads(1, Asm, Bsm, Ahi, Alo, Bhi, Blo, bm0, n0, tid);
    for (int i = 0; i < NCH; ++i) {
        if (i + 1 < NCH) CP_WAIT1(); else CP_WAIT0();
        __syncthreads();
        if (i + 2 < NCH)
            issue_tile_loads(i + 2, Asm, Bsm, Ahi, Alo, Bhi, Blo, bm0, n0, tid);
        const int s = i % NSTG;
        compute_chunk(Asm + s * STG_BYTES, Bsm + s * STG_BYTES, wm, wn, lane, acc);
    }
}

// ---------------- prep kernels -------------------------------------------------
__global__ void prep_w_kernel(const float* __restrict__ W_hh,
                              const float* __restrict__ W_out,
                              const float* __restrict__ b_ih,
                              const float* __restrict__ b_hh) {
    const size_t nW = (size_t)NG * KH;
    for (size_t i = (size_t)blockIdx.x * blockDim.x + threadIdx.x; i < nW;
         i += (size_t)gridDim.x * blockDim.x) {
        int n = (int)(i >> 9), k = (int)(i & 511);
        int h = n >> 2, g = n & 3;
        split_bf16(W_hh[(size_t)(g * HDIM + h) * HDIM + k], g_Whi[i], g_Wlo[i]);
    }
    const size_t nWo = (size_t)VOCAB * KH;
    for (size_t i = (size_t)blockIdx.x * blockDim.x + threadIdx.x; i < nWo;
         i += (size_t)gridDim.x * blockDim.x) {
        split_bf16(W_out[i], g_Wohi[i], g_Wolo[i]);
    }
    int j = blockIdx.x * blockDim.x + threadIdx.x;
    if (j < NG) {
        int h = j >> 2, g = j & 3;
        g_bsum[j] = b_ih[g * HDIM + h] + b_hh[g * HDIM + h];
    }
}

__global__ void prep_h_kernel(const float* __restrict__ h0, const float* __restrict__ c0) {
    const size_t n = (size_t)BATCH * HDIM;
    for (size_t i = (size_t)blockIdx.x * blockDim.x + threadIdx.x; i < n;
         i += (size_t)gridDim.x * blockDim.x) {
        split_bf16(h0[i], g_Ahi[i], g_Alo[i]);
        g_C[i] = c0[i];
    }
}

__global__ void xg_tab_kernel(const float* __restrict__ emb, const float* __restrict__ W_ih) {
    int i = blockIdx.x * blockDim.x + threadIdx.x;
    if (i >= VOCAB * NG) return;
    int v = i >> 11, n = i & (NG - 1);
    int h = n >> 2, g = n & 3;
    const float* er = emb + (size_t)v * EDIM;
    const float* wr = W_ih + (size_t)(g * HDIM + h) * EDIM;
    float s = 0.0f;
    #pragma unroll
    for (int e = 0; e < EDIM; ++e) s += er[e] * wr[e];
    g_Xg[i] = s;
}

// ---------------- fused step kernel -------------------------------------------
// by 0..15: gate GEMM tile (n0 = by*128) + LSTM cell epilogue (writes h[t+1], c)
// by == 16: output projection of h[t] -> scores[t-1]  (skipped at t==0)
#define SC_STRIDE 132
__global__ __launch_bounds__(256, 2)
void lstm_step_kernel(int t, const int* __restrict__ input,
                      const float* __restrict__ b_out, float* __restrict__ out) {
    extern __shared__ char dsm[];
    const uint32_t tile = (smem_u32(dsm) + 1023) & ~1023u;
    const uint32_t Asm = tile;                        // NSTG x 16384
    const uint32_t Bsm = tile + NSTG * STG_BYTES;     // NSTG x 16384
    float* sC = reinterpret_cast<float*>(dsm + (tile - smem_u32(dsm)));  // epilogue reuse

    const int tid  = threadIdx.x;
    const int lane = tid & 31;
    const int w    = tid >> 5;
    const int wm   = (w & 1) * 64;
    const int wn   = (w >> 1) * 32;
    const int bm0  = blockIdx.x * 128;
    const int by   = blockIdx.y;

    const __nv_bfloat16* Ahi = g_Ahi + (size_t)t * BATCH * KH;
    const __nv_bfloat16* Alo = g_Alo + (size_t)t * BATCH * KH;

    float acc[4][4][4];
    #pragma unroll
    for (int mi = 0; mi < 4; ++mi)
        #pragma unroll
        for (int nj = 0; nj < 4; ++nj)
            #pragma unroll
            for (int q = 0; q < 4; ++q) acc[mi][nj][q] = 0.0f;

    if (by == 16) {
        // ---- output projection of h[t] -> scores[t-1] ----
        if (t == 0) return;
        run_mainloop(Ahi, Alo, g_Wohi, g_Wolo, bm0, 0, tid, lane, wm, wn, Asm, Bsm, acc);
        const size_t rowbase = (size_t)(t - 1) * BATCH + bm0;
        #pragma unroll
        for (int mi = 0; mi < 4; ++mi)
            #pragma unroll
            for (int nj = 0; nj < 4; ++nj) {
                int r0 = wm + 16 * mi + (lane >> 2);
                int c  = wn + 8 * nj + 2 * (lane & 3);
                float2 bo = *reinterpret_cast<const float2*>(&b_out[c]);
                *reinterpret_cast<float2*>(&out[(rowbase + r0) * VOCAB + c]) =
                    make_float2(acc[mi][nj][0] + bo.x, acc[mi][nj][1] + bo.y);
                *reinterpret_cast<float2*>(&out[(rowbase + r0 + 8) * VOCAB + c]) =
                    make_float2(acc[mi][nj][2] + bo.x, acc[mi][nj][3] + bo.y);
            }
        return;
    }

    const int n0 = by * 128;
    run_mainloop(Ahi, Alo, g_Whi, g_Wlo, bm0, n0, tid, lane, wm, wn, Asm, Bsm, acc);

    // ---- epilogue: regroup gates via smem, apply LSTM cell ----
    __syncthreads();   // all warps done with tile buffers before sC overwrite
    #pragma unroll
    for (int mi = 0; mi < 4; ++mi)
        #pragma unroll
        for (int nj = 0; nj < 4; ++nj) {
            int r0 = wm + 16 * mi + (lane >> 2);
            int c  = wn + 8 * nj + 2 * (lane & 3);
            *reinterpret_cast<float2*>(&sC[r0 * SC_STRIDE + c]) =
                make_float2(acc[mi][nj][0], acc[mi][nj][1]);
            *reinterpret_cast<float2*>(&sC[(r0 + 8) * SC_STRIDE + c]) =
                make_float2(acc[mi][nj][2], acc[mi][nj][3]);
        }
    __syncthreads();

    const int m = tid >> 1;
    const int half = tid & 1;
    const int b = bm0 + m;
    const int v = input[(size_t)t * BATCH + b];
    const int hbase = (n0 >> 2) + half * 16;       // 16 consecutive h per thread
    __nv_bfloat16* Hhi = g_Ahi + (size_t)(t + 1) * BATCH * KH + (size_t)b * KH + hbase;
    __nv_bfloat16* Hlo = g_Alo + (size_t)(t + 1) * BATCH * KH + (size_t)b * KH + hbase;
    float* Crow = g_C + (size_t)b * HDIM + hbase;

    __align__(16) __nv_bfloat16 hh[16], hl[16];
    __align__(16) float cn16[16];
    #pragma unroll
    for (int i = 0; i < 16; ++i) {
        const int lh = half * 16 + i;              // local h in tile (0..31)
        float4 gq = *reinterpret_cast<const float4*>(&sC[m * SC_STRIDE + lh * 4]);
        const int n = n0 + lh * 4;
        float4 bs = *reinterpret_cast<const float4*>(&g_bsum[n]);
        float4 xg = *reinterpret_cast<const float4*>(&g_Xg[(size_t)v * NG + n]);
        float gi = gq.x + bs.x + xg.x;
        float gf = gq.y + bs.y + xg.y;
        float gg = gq.z + bs.z + xg.z;
        float go = gq.w + bs.w + xg.w;
        float cn = sigm(gf) * Crow[i] + sigm(gi) * tanh_fast(gg);
        cn16[i] = cn;
        split_bf16(sigm(go) * tanh_fast(cn), hh[i], hl[i]);
    }
    #pragma unroll
    for (int q = 0; q < 4; ++q)
        *reinterpret_cast<float4*>(&Crow[q * 4]) = *reinterpret_cast<float4*>(&cn16[q * 4]);
    *reinterpret_cast<uint4*>(&Hhi[0]) = *reinterpret_cast<uint4*>(&hh[0]);
    *reinterpret_cast<uint4*>(&Hhi[8]) = *reinterpret_cast<uint4*>(&hh[8]);
    *reinterpret_cast<uint4*>(&Hlo[0]) = *reinterpret_cast<uint4*>(&hl[0]);
    *reinterpret_cast<uint4*>(&Hlo[8]) = *reinterpret_cast<uint4*>(&hl[8]);
}

// ---------------- last-step output projection ----------------------------------
__global__ __launch_bounds__(256, 2)
void out_last_kernel(const float* __restrict__ b_out, float* __restrict__ out) {
    extern __shared__ char dsm[];
    const uint32_t tile = (smem_u32(dsm) + 1023) & ~1023u;
    const uint32_t Asm = tile;
    const uint32_t Bsm = tile + NSTG * STG_BYTES;

    const int tid  = threadIdx.x;
    const int lane = tid & 31;
    const int w    = tid >> 5;
    const int wm   = (w & 1) * 64;
    const int wn   = (w >> 1) * 32;
    const int bm0  = blockIdx.x * 128;

    const __nv_bfloat16* Ahi = g_Ahi + (size_t)LSEQ * BATCH * KH;
    const __nv_bfloat16* Alo = g_Alo + (size_t)LSEQ * BATCH * KH;

    float acc[4][4][4];
    #pragma unroll
    for (int mi = 0; mi < 4; ++mi)
        #pragma unroll
        for (int nj = 0; nj < 4; ++nj)
            #pragma unroll
            for (int q = 0; q < 4; ++q) acc[mi][nj][q] = 0.0f;

    run_mainloop(Ahi, Alo, g_Wohi, g_Wolo, bm0, 0, tid, lane, wm, wn, Asm, Bsm, acc);

    const size_t rowbase = (size_t)(LSEQ - 1) * BATCH + bm0;
    #pragma unroll
    for (int mi = 0; mi < 4; ++mi)
        #pragma unroll
        for (int nj = 0; nj < 4; ++nj) {
            int r0 = wm + 16 * mi + (lane >> 2);
            int c  = wn + 8 * nj + 2 * (lane & 3);
            float2 bo = *reinterpret_cast<const float2*>(&b_out[c]);
            *reinterpret_cast<float2*>(&out[(rowbase + r0) * VOCAB + c]) =
                make_float2(acc[mi][nj][0] + bo.x, acc[mi][nj][1] + bo.y);
            *reinterpret_cast<float2*>(&out[(rowbase + r0 + 8) * VOCAB + c]) =
                make_float2(acc[mi][nj][2] + bo.x, acc[mi][nj][3] + bo.y);
        }
}

// ---------------- tail: final h (hi+lo) and c ---------------------------------
__global__ void tail_kernel(float* __restrict__ out) {
    const size_t baseH = (size_t)LSEQ * BATCH * VOCAB;
    const size_t n = (size_t)BATCH * HDIM;
    const __nv_bfloat16* Hhi = g_Ahi + (size_t)LSEQ * BATCH * KH;
    const __nv_bfloat16* Hlo = g_Alo + (size_t)LSEQ * BATCH * KH;
    for (size_t i = (size_t)blockIdx.x * blockDim.x + threadIdx.x; i < n;
         i += (size_t)gridDim.x * blockDim.x) {
        out[baseH + i] = __bfloat162float(Hhi[i]) + __bfloat162float(Hlo[i]);
        out[baseH + n + i] = g_C[i];
    }
}

// ---------------- launch -------------------------------------------------------
extern "C" void kernel_launch(void* const* d_in, const int* in_sizes, int n_in,
                              void* d_out, int out_size) {
    const int*   input = (const int*)  d_in[0];
    const float* h0    = (const float*)d_in[1];
    const float* c0    = (const float*)d_in[2];
    const float* emb   = (const float*)d_in[3];
    const float* W_ih  = (const float*)d_in[4];
    const float* W_hh  = (const float*)d_in[5];
    const float* b_ih  = (const float*)d_in[6];
    const float* b_hh  = (const float*)d_in[7];
    const float* W_out = (const float*)d_in[8];
    const float* b_out = (const float*)d_in[9];
    float* out = (float*)d_out;

    // 1KB align pad + 3-stage A/B tiles (96KB); sC (67.6KB) reuses tile space
    const int smem_bytes = 1024 + 2 * NSTG * STG_BYTES;
    cudaFuncSetAttribute(lstm_step_kernel, cudaFuncAttributeMaxDynamicSharedMemorySize, smem_bytes);
    cudaFuncSetAttribute(out_last_kernel, cudaFuncAttributeMaxDynamicSharedMemorySize, smem_bytes);

    prep_w_kernel<<<1024, 256>>>(W_hh, W_out, b_ih, b_hh);
    prep_h_kernel<<<1024, 256>>>(h0, c0);
    xg_tab_kernel<<<(VOCAB * NG) / 256, 256>>>(emb, W_ih);

    dim3 stepGrid(BATCH / 128, 17);  // by 0..15: gates; by 16: out-proj of h[t]
    for (int t = 0; t < LSEQ; ++t) {
        lstm_step_kernel<<<stepGrid, 256, smem_bytes>>>(t, input, b_out, out);
    }

    out_last_kernel<<<BATCH / 128, 256, smem_bytes>>>(b_out, out);
    tail_kernel<<<4096, 256>>>(out);
}

// round 7
// speedup vs baseline: 1.7733x; 1.7733x over previous
#include <cuda_runtime.h>
#include <cuda_bf16.h>
#include <cstdint>
#include <math.h>

// Problem constants
#define LSEQ 48
#define BATCH 8192
#define EDIM 50
#define HDIM 512
#define VOCAB 128
#define NG   (4 * HDIM)      // 2048 packed gate columns (n = h*4 + g)
#define KQ   512             // K per limb
#define NCHI 12              // 12 chunks of 128 bytes: 4x(x1w1) + 4x(x1w2) + 4x(x2w1)
#define NSTG 3               // pipeline stages
#define STG_BYTES 16384      // bytes per stage per operand (128 rows x 128B)

// ---------------- scratch (static __device__ arrays; no allocation) ----------
__device__ signed char g_W1[(size_t)NG * KQ];        // W_hh limb1, packed [n][k]
__device__ signed char g_W2[(size_t)NG * KQ];        // limb2
__device__ signed char g_Wo1[(size_t)VOCAB * KQ];    // W_out limb1 [v][k]
__device__ signed char g_Wo2[(size_t)VOCAB * KQ];    // limb2
__device__ float g_bsum[NG];                         // b_ih + b_hh, packed order
__device__ float g_Xg[(size_t)VOCAB * NG];           // emb @ W_ih^T, packed order
__device__ signed char g_A1[(size_t)(LSEQ + 1) * BATCH * KQ];  // h limb1 [t][b][k]
__device__ signed char g_A2[(size_t)(LSEQ + 1) * BATCH * KQ];  // limb2
__device__ float g_C[(size_t)BATCH * HDIM];          // cell state [b][h] fp32
__device__ float g_Hlast[(size_t)BATCH * HDIM];      // final h fp32 (for output)
__device__ unsigned g_swbits[2];                     // max|W_hh|, max|W_out| as uint bits

#define SX (128.0f / 127.0f)

// ---------------- helpers ----------------------------------------------------
__device__ __forceinline__ uint32_t smem_u32(const void* p) {
    return (uint32_t)__cvta_generic_to_shared(p);
}
#define CP16(dst, src) asm volatile("cp.async.cg.shared.global [%0], [%1], 16;" :: "r"(dst), "l"(src))
#define CP_COMMIT()    asm volatile("cp.async.commit_group;")
#define CP_WAIT0()     asm volatile("cp.async.wait_group 0;" ::: "memory")
#define CP_WAIT1()     asm volatile("cp.async.wait_group 1;" ::: "memory")

__device__ __forceinline__ void ldsm4(uint32_t& r0, uint32_t& r1, uint32_t& r2, uint32_t& r3,
                                      uint32_t addr) {
    asm volatile("ldmatrix.sync.aligned.m8n8.x4.shared.b16 {%0,%1,%2,%3}, [%4];"
                 : "=r"(r0), "=r"(r1), "=r"(r2), "=r"(r3) : "r"(addr));
}
__device__ __forceinline__ void imma16832(int* d, const uint32_t* a, uint32_t b0, uint32_t b1) {
    asm volatile("mma.sync.aligned.m16n8k32.row.col.s32.s8.s8.s32 "
                 "{%0,%1,%2,%3}, {%4,%5,%6,%7}, {%8,%9}, {%0,%1,%2,%3};"
                 : "+r"(d[0]), "+r"(d[1]), "+r"(d[2]), "+r"(d[3])
                 : "r"(a[0]), "r"(a[1]), "r"(a[2]), "r"(a[3]), "r"(b0), "r"(b1));
}
__device__ __forceinline__ float sigm(float x) { return 1.0f / (1.0f + __expf(-x)); }
__device__ __forceinline__ float tanh_fast(float x) { return 2.0f * sigm(2.0f * x) - 1.0f; }

__device__ __forceinline__ float load_sw(int idx) {
    return __uint_as_float(g_swbits[idx]) * SX * 1.0000005f;
}
// quantize u (|u| <= ~127/128) into 2 int8 limbs: u ~= q1*2^-7 + q2*2^-14
__device__ __forceinline__ void quant_u(float u, int& q1, int& q2) {
    int x1 = __float2int_rn(u * 128.0f);
    x1 = min(127, max(-127, x1));
    float r = u - (float)x1 * 0.0078125f;
    int x2 = __float2int_rn(r * 16384.0f);
    q1 = x1;
    q2 = min(127, max(-127, x2));
}

// ---------------- cp.async tile loader (int8 chunk -> swizzled SMEM) ----------
// chunk 0-3: A1*W1, 4-7: A1*W2, 8-11: A2*W1.  BK=128 bytes, 128B rows.
__device__ __forceinline__ void issue_tile_loads(
    int chunk, uint32_t Asm, uint32_t Bsm,
    const signed char* __restrict__ A1, const signed char* __restrict__ A2,
    const signed char* __restrict__ B1, const signed char* __restrict__ B2,
    int bm0, int n0, int tid)
{
    const int seg = chunk >> 2;
    const int k0  = (chunk & 3) * 128;
    const int s   = chunk % NSTG;
    const signed char* Ab = (seg < 2) ? A1 : A2;
    const signed char* Bb = (seg == 1) ? B2 : B1;
    const int r    = tid >> 1;             // 0..127
    const int boff = (tid & 1) * 64;       // byte offset within 128B row-chunk
    const signed char* ga = Ab + ((size_t)(bm0 + r) << 9) + k0 + boff;
    const signed char* gb = Bb + ((size_t)(n0 + r) << 9) + k0 + boff;
    const uint32_t abase = Asm + s * STG_BYTES, bbase = Bsm + s * STG_BYTES;
    #pragma unroll
    for (int j = 0; j < 4; ++j) {
        uint32_t off = r * 128 + boff + j * 16;
        uint32_t sw  = off ^ ((off >> 3) & 0x70);
        CP16(abase + sw, ga + j * 16);
        CP16(bbase + sw, gb + j * 16);
    }
    CP_COMMIT();
}

// ---------------- one BK=128B chunk of IMMA compute ---------------------------
// Warp tile 64(m) x 32(n); 4 kk of k32; addressing identical to verified bf16
// layout (byte units): A frag regs = rows{0-7,8-15} x bytes{0-15,16-31}.
__device__ __forceinline__ void compute_chunk(uint32_t sAb, uint32_t sBb,
                                              int wm, int wn, int lane,
                                              int acc[4][4][4]) {
    #pragma unroll
    for (int kk = 0; kk < 4; ++kk) {
        uint32_t a[4][4];
        #pragma unroll
        for (int mi = 0; mi < 4; ++mi) {
            int r  = wm + 16 * mi + (lane & 15);
            int kb = kk * 32 + ((lane >> 4) << 4);
            uint32_t off = (uint32_t)(r * 128 + kb);
            off ^= (off >> 3) & 0x70;
            ldsm4(a[mi][0], a[mi][1], a[mi][2], a[mi][3], sAb + off);
        }
        uint32_t b[2][4];
        #pragma unroll
        for (int nj2 = 0; nj2 < 2; ++nj2) {
            int r  = wn + nj2 * 16 + ((lane >> 4) << 3) + (lane & 7);
            int kb = kk * 32 + ((lane & 8) ? 16 : 0);
            uint32_t off = (uint32_t)(r * 128 + kb);
            off ^= (off >> 3) & 0x70;
            ldsm4(b[nj2][0], b[nj2][1], b[nj2][2], b[nj2][3], sBb + off);
        }
        #pragma unroll
        for (int mi = 0; mi < 4; ++mi)
            #pragma unroll
            for (int nj = 0; nj < 4; ++nj)
                imma16832(acc[mi][nj], a[mi],
                          b[nj >> 1][(nj & 1) * 2], b[nj >> 1][(nj & 1) * 2 + 1]);
    }
}

// ---------------- mainloop: 12 chunks, acc<<7 between P and Q phases ----------
__device__ __forceinline__ void run_mainloop(
    const signed char* __restrict__ A1, const signed char* __restrict__ A2,
    const signed char* __restrict__ B1, const signed char* __restrict__ B2,
    int bm0, int n0, int tid, int lane, int wm, int wn,
    uint32_t Asm, uint32_t Bsm, int acc[4][4][4])
{
    issue_tile_loads(0, Asm, Bsm, A1, A2, B1, B2, bm0, n0, tid);
    issue_tile_loads(1, Asm, Bsm, A1, A2, B1, B2, bm0, n0, tid);
    for (int i = 0; i < NCHI; ++i) {
        if (i + 1 < NCHI) CP_WAIT1(); else CP_WAIT0();
        __syncthreads();
        if (i + 2 < NCHI)
            issue_tile_loads(i + 2, Asm, Bsm, A1, A2, B1, B2, bm0, n0, tid);
        if (i == 4) {  // P phase done: gates = c2*(128*P + Q)
            #pragma unroll
            for (int mi = 0; mi < 4; ++mi)
                #pragma unroll
                for (int nj = 0; nj < 4; ++nj)
                    #pragma unroll
                    for (int q = 0; q < 4; ++q) acc[mi][nj][q] <<= 7;
        }
        const int s = i % NSTG;
        compute_chunk(Asm + s * STG_BYTES, Bsm + s * STG_BYTES, wm, wn, lane, acc);
    }
}

// ---------------- prep kernels -------------------------------------------------
__global__ void scale_init_kernel() {
    if (threadIdx.x < 2) g_swbits[threadIdx.x] = 0u;
}
__global__ void scale_max_kernel(const float* __restrict__ W_hh,
                                 const float* __restrict__ W_out) {
    unsigned lm0 = 0, lm1 = 0;
    for (size_t i = (size_t)blockIdx.x * blockDim.x + threadIdx.x; i < (size_t)NG * KQ;
         i += (size_t)gridDim.x * blockDim.x)
        lm0 = max(lm0, __float_as_uint(fabsf(W_hh[i])));
    for (size_t i = (size_t)blockIdx.x * blockDim.x + threadIdx.x; i < (size_t)VOCAB * KQ;
         i += (size_t)gridDim.x * blockDim.x)
        lm1 = max(lm1, __float_as_uint(fabsf(W_out[i])));
    if (lm0) atomicMax(&g_swbits[0], lm0);
    if (lm1) atomicMax(&g_swbits[1], lm1);
}

__global__ void prep_w_kernel(const float* __restrict__ W_hh,
                              const float* __restrict__ W_out,
                              const float* __restrict__ b_ih,
                              const float* __restrict__ b_hh) {
    const float sw  = load_sw(0);
    const float swo = load_sw(1);
    const size_t nW = (size_t)NG * KQ;
    for (size_t i = (size_t)blockIdx.x * blockDim.x + threadIdx.x; i < nW;
         i += (size_t)gridDim.x * blockDim.x) {
        int n = (int)(i >> 9), k = (int)(i & 511);
        int h = n >> 2, g = n & 3;
        int q1, q2;
        quant_u(W_hh[(size_t)(g * HDIM + h) * HDIM + k] / sw, q1, q2);
        g_W1[i] = (signed char)q1;
        g_W2[i] = (signed char)q2;
    }
    const size_t nWo = (size_t)VOCAB * KQ;
    for (size_t i = (size_t)blockIdx.x * blockDim.x + threadIdx.x; i < nWo;
         i += (size_t)gridDim.x * blockDim.x) {
        int q1, q2;
        quant_u(W_out[i] / swo, q1, q2);
        g_Wo1[i] = (signed char)q1;
        g_Wo2[i] = (signed char)q2;
    }
    int j = blockIdx.x * blockDim.x + threadIdx.x;
    if (j < NG) {
        int h = j >> 2, g = j & 3;
        g_bsum[j] = b_ih[g * HDIM + h] + b_hh[g * HDIM + h];
    }
}

__global__ void prep_h_kernel(const float* __restrict__ h0, const float* __restrict__ c0) {
    const size_t n = (size_t)BATCH * HDIM;
    for (size_t i = (size_t)blockIdx.x * blockDim.x + threadIdx.x; i < n;
         i += (size_t)gridDim.x * blockDim.x) {
        int q1, q2;
        quant_u(h0[i] * (127.0f / 128.0f), q1, q2);
        g_A1[i] = (signed char)q1;
        g_A2[i] = (signed char)q2;
        g_C[i] = c0[i];
    }
}

__global__ void xg_tab_kernel(const float* __restrict__ emb, const float* __restrict__ W_ih) {
    int i = blockIdx.x * blockDim.x + threadIdx.x;
    if (i >= VOCAB * NG) return;
    int v = i >> 11, n = i & (NG - 1);
    int h = n >> 2, g = n & 3;
    const float* er = emb + (size_t)v * EDIM;
    const float* wr = W_ih + (size_t)(g * HDIM + h) * EDIM;
    float s = 0.0f;
    #pragma unroll
    for (int e = 0; e < EDIM; ++e) s += er[e] * wr[e];
    g_Xg[i] = s;
}

// ---------------- fused step kernel -------------------------------------------
// by 0..15: gate GEMM tile + LSTM cell epilogue; by==16: out-proj h[t]->scores[t-1]
#define SC_STRIDE 132
__global__ __launch_bounds__(256, 2)
void lstm_step_kernel(int t, const int* __restrict__ input,
                      const float* __restrict__ b_out, float* __restrict__ out) {
    extern __shared__ char dsm[];
    const uint32_t tile = (smem_u32(dsm) + 1023) & ~1023u;
    const uint32_t Asm = tile;                        // NSTG x 16KB
    const uint32_t Bsm = tile + NSTG * STG_BYTES;     // NSTG x 16KB
    float* sC = reinterpret_cast<float*>(dsm + (tile - smem_u32(dsm)));  // epilogue reuse

    const int tid  = threadIdx.x;
    const int lane = tid & 31;
    const int w    = tid >> 5;
    const int wm   = (w & 1) * 64;
    const int wn   = (w >> 1) * 32;
    const int bm0  = blockIdx.x * 128;
    const int by   = blockIdx.y;

    const signed char* A1 = g_A1 + (size_t)t * BATCH * KQ;
    const signed char* A2 = g_A2 + (size_t)t * BATCH * KQ;

    int acc[4][4][4];
    #pragma unroll
    for (int mi = 0; mi < 4; ++mi)
        #pragma unroll
        for (int nj = 0; nj < 4; ++nj)
            #pragma unroll
            for (int q = 0; q < 4; ++q) acc[mi][nj][q] = 0;

    if (by == 16) {
        if (t == 0) return;
        run_mainloop(A1, A2, g_Wo1, g_Wo2, bm0, 0, tid, lane, wm, wn, Asm, Bsm, acc);
        const float c2 = SX * load_sw(1) * (1.0f / 2097152.0f);
        const size_t rowbase = (size_t)(t - 1) * BATCH + bm0;
        #pragma unroll
        for (int mi = 0; mi < 4; ++mi)
            #pragma unroll
            for (int nj = 0; nj < 4; ++nj) {
                int r0 = wm + 16 * mi + (lane >> 2);
                int c  = wn + 8 * nj + 2 * (lane & 3);
                float2 bo = *reinterpret_cast<const float2*>(&b_out[c]);
                *reinterpret_cast<float2*>(&out[(rowbase + r0) * VOCAB + c]) =
                    make_float2(c2 * (float)acc[mi][nj][0] + bo.x,
                                c2 * (float)acc[mi][nj][1] + bo.y);
                *reinterpret_cast<float2*>(&out[(rowbase + r0 + 8) * VOCAB + c]) =
                    make_float2(c2 * (float)acc[mi][nj][2] + bo.x,
                                c2 * (float)acc[mi][nj][3] + bo.y);
            }
        return;
    }

    const int n0 = by * 128;
    run_mainloop(A1, A2, g_W1, g_W2, bm0, n0, tid, lane, wm, wn, Asm, Bsm, acc);

    // ---- epilogue: scale to float, regroup gates via smem, apply LSTM cell ----
    const float c2 = SX * load_sw(0) * (1.0f / 2097152.0f);
    __syncthreads();   // all warps done with tile buffers before sC overwrite
    #pragma unroll
    for (int mi = 0; mi < 4; ++mi)
        #pragma unroll
        for (int nj = 0; nj < 4; ++nj) {
            int r0 = wm + 16 * mi + (lane >> 2);
            int c  = wn + 8 * nj + 2 * (lane & 3);
            *reinterpret_cast<float2*>(&sC[r0 * SC_STRIDE + c]) =
                make_float2(c2 * (float)acc[mi][nj][0], c2 * (float)acc[mi][nj][1]);
            *reinterpret_cast<float2*>(&sC[(r0 + 8) * SC_STRIDE + c]) =
                make_float2(c2 * (float)acc[mi][nj][2], c2 * (float)acc[mi][nj][3]);
        }
    __syncthreads();

    const int m = tid >> 1;
    const int half = tid & 1;
    const int b = bm0 + m;
    const int v = input[(size_t)t * BATCH + b];
    const int hbase = (n0 >> 2) + half * 16;       // 16 consecutive h per thread
    signed char* H1 = g_A1 + (size_t)(t + 1) * BATCH * KQ + (size_t)b * KQ + hbase;
    signed char* H2 = g_A2 + (size_t)(t + 1) * BATCH * KQ + (size_t)b * KQ + hbase;
    float* Crow = g_C + (size_t)b * HDIM + hbase;

    __align__(16) signed char q1v[16], q2v[16];
    __align__(16) float cn16[16], hv[16];
    #pragma unroll
    for (int i = 0; i < 16; ++i) {
        const int lh = half * 16 + i;              // local h in tile (0..31)
        float4 gq = *reinterpret_cast<const float4*>(&sC[m * SC_STRIDE + lh * 4]);
        const int n = n0 + lh * 4;
        float4 bs = *reinterpret_cast<const float4*>(&g_bsum[n]);
        float4 xg = *reinterpret_cast<const float4*>(&g_Xg[(size_t)v * NG + n]);
        float gi = gq.x + bs.x + xg.x;
        float gf = gq.y + bs.y + xg.y;
        float gg = gq.z + bs.z + xg.z;
        float go = gq.w + bs.w + xg.w;
        float cn = sigm(gf) * Crow[i] + sigm(gi) * tanh_fast(gg);
        cn16[i] = cn;
        float hn = sigm(go) * tanh_fast(cn);
        hv[i] = hn;
        int q1, q2;
        quant_u(hn * (127.0f / 128.0f), q1, q2);
        q1v[i] = (signed char)q1;
        q2v[i] = (signed char)q2;
    }
    #pragma unroll
    for (int q = 0; q < 4; ++q)
        *reinterpret_cast<float4*>(&Crow[q * 4]) = *reinterpret_cast<float4*>(&cn16[q * 4]);
    *reinterpret_cast<uint4*>(H1) = *reinterpret_cast<uint4*>(q1v);
    *reinterpret_cast<uint4*>(H2) = *reinterpret_cast<uint4*>(q2v);
    if (t == LSEQ - 1) {
        float* HL = g_Hlast + (size_t)b * HDIM + hbase;
        #pragma unroll
        for (int q = 0; q < 4; ++q)
            *reinterpret_cast<float4*>(&HL[q * 4]) = *reinterpret_cast<float4*>(&hv[q * 4]);
    }
}

// ---------------- last-step output projection ----------------------------------
__global__ __launch_bounds__(256, 2)
void out_last_kernel(const float* __restrict__ b_out, float* __restrict__ out) {
    extern __shared__ char dsm[];
    const uint32_t tile = (smem_u32(dsm) + 1023) & ~1023u;
    const uint32_t Asm = tile;
    const uint32_t Bsm = tile + NSTG * STG_BYTES;

    const int tid  = threadIdx.x;
    const int lane = tid & 31;
    const int w    = tid >> 5;
    const int wm   = (w & 1) * 64;
    const int wn   = (w >> 1) * 32;
    const int bm0  = blockIdx.x * 128;

    const signed char* A1 = g_A1 + (size_t)LSEQ * BATCH * KQ;
    const signed char* A2 = g_A2 + (size_t)LSEQ * BATCH * KQ;

    int acc[4][4][4];
    #pragma unroll
    for (int mi = 0; mi < 4; ++mi)
        #pragma unroll
        for (int nj = 0; nj < 4; ++nj)
            #pragma unroll
            for (int q = 0; q < 4; ++q) acc[mi][nj][q] = 0;

    run_mainloop(A1, A2, g_Wo1, g_Wo2, bm0, 0, tid, lane, wm, wn, Asm, Bsm, acc);

    const float c2 = SX * load_sw(1) * (1.0f / 2097152.0f);
    const size_t rowbase = (size_t)(LSEQ - 1) * BATCH + bm0;
    #pragma unroll
    for (int mi = 0; mi < 4; ++mi)
        #pragma unroll
        for (int nj = 0; nj < 4; ++nj) {
            int r0 = wm + 16 * mi + (lane >> 2);
            int c  = wn + 8 * nj + 2 * (lane & 3);
            float2 bo = *reinterpret_cast<const float2*>(&b_out[c]);
            *reinterpret_cast<float2*>(&out[(rowbase + r0) * VOCAB + c]) =
                make_float2(c2 * (float)acc[mi][nj][0] + bo.x,
                            c2 * (float)acc[mi][nj][1] + bo.y);
            *reinterpret_cast<float2*>(&out[(rowbase + r0 + 8) * VOCAB + c]) =
                make_float2(c2 * (float)acc[mi][nj][2] + bo.x,
                            c2 * (float)acc[mi][nj][3] + bo.y);
        }
}

// ---------------- tail: final h (fp32) and c -----------------------------------
__global__ void tail_kernel(float* __restrict__ out) {
    const size_t baseH = (size_t)LSEQ * BATCH * VOCAB;
    const size_t n = (size_t)BATCH * HDIM;
    for (size_t i = (size_t)blockIdx.x * blockDim.x + threadIdx.x; i < n;
         i += (size_t)gridDim.x * blockDim.x) {
        out[baseH + i] = g_Hlast[i];
        out[baseH + n + i] = g_C[i];
    }
}

// ---------------- launch -------------------------------------------------------
extern "C" void kernel_launch(void* const* d_in, const int* in_sizes, int n_in,
                              void* d_out, int out_size) {
    const int*   input = (const int*)  d_in[0];
    const float* h0    = (const float*)d_in[1];
    const float* c0    = (const float*)d_in[2];
    const float* emb   = (const float*)d_in[3];
    const float* W_ih  = (const float*)d_in[4];
    const float* W_hh  = (const float*)d_in[5];
    const float* b_ih  = (const float*)d_in[6];
    const float* b_hh  = (const float*)d_in[7];
    const float* W_out = (const float*)d_in[8];
    const float* b_out = (const float*)d_in[9];
    float* out = (float*)d_out;

    // 1KB align pad + 3-stage A/B int8 tiles (96KB); sC (67.6KB) reuses tile space
    const int smem_bytes = 1024 + 2 * NSTG * STG_BYTES;
    cudaFuncSetAttribute(lstm_step_kernel, cudaFuncAttributeMaxDynamicSharedMemorySize, smem_bytes);
    cudaFuncSetAttribute(out_last_kernel, cudaFuncAttributeMaxDynamicSharedMemorySize, smem_bytes);

    scale_init_kernel<<<1, 32>>>();
    scale_max_kernel<<<512, 256>>>(W_hh, W_out);
    prep_w_kernel<<<1024, 256>>>(W_hh, W_out, b_ih, b_hh);
    prep_h_kernel<<<1024, 256>>>(h0, c0);
    xg_tab_kernel<<<(VOCAB * NG) / 256, 256>>>(emb, W_ih);

    dim3 stepGrid(BATCH / 128, 17);  // by 0..15: gates; by 16: out-proj of h[t]
    for (int t = 0; t < LSEQ; ++t) {
        lstm_step_kernel<<<stepGrid, 256, smem_bytes>>>(t, input, b_out, out);
    }

    out_last_kernel<<<BATCH / 128, 256, smem_bytes>>>(b_out, out);
    tail_kernel<<<4096, 256>>>(out);
}